// round 1
// baseline (speedup 1.0000x reference)
#include <cuda_runtime.h>

// RingAttention == exact causal attention. B=2, S=8192, H=16, D=64, fp32.
// Flash-attention forward, one thread per query row, f32x2 packed math.

#define BR 128          // query rows per block == threads per block
#define BC 64           // keys per smem tile
#define HD 64           // head dim
#define S_LEN 8192
#define NHEAD 16

// ---- packed f32x2 helpers (Blackwell FFMA2 path) ----
__device__ __forceinline__ unsigned long long fma2(unsigned long long a,
                                                   unsigned long long b,
                                                   unsigned long long c) {
    unsigned long long d;
    asm("fma.rn.f32x2 %0, %1, %2, %3;" : "=l"(d) : "l"(a), "l"(b), "l"(c));
    return d;
}
__device__ __forceinline__ unsigned long long mul2(unsigned long long a,
                                                   unsigned long long b) {
    unsigned long long d;
    asm("mul.rn.f32x2 %0, %1, %2;" : "=l"(d) : "l"(a), "l"(b));
    return d;
}
__device__ __forceinline__ unsigned long long pack2(float lo, float hi) {
    unsigned long long d;
    asm("mov.b64 %0, {%1, %2};" : "=l"(d) : "f"(lo), "f"(hi));
    return d;
}
__device__ __forceinline__ float2 unpack2(unsigned long long v) {
    float lo, hi;
    asm("mov.b64 {%0, %1}, %2;" : "=f"(lo), "=f"(hi) : "l"(v));
    return make_float2(lo, hi);
}

__global__ __launch_bounds__(BR) void ring_attn_fwd(
    const float* __restrict__ Q,
    const float* __restrict__ K,
    const float* __restrict__ V,
    float* __restrict__ O)
{
    __shared__ __align__(16) float sK[BC][HD];
    __shared__ __align__(16) float sV[BC][HD];

    // heavy (high qtile) blocks first to reduce wave-tail imbalance
    const int qtile = (int)gridDim.x - 1 - (int)blockIdx.x;
    const int h = blockIdx.y;
    const int b = blockIdx.z;
    const int t = threadIdx.x;
    const int qg = qtile * BR + t;  // global query row for this thread

    const size_t rowStride = (size_t)NHEAD * HD;  // floats per sequence position
    const float* qptr = Q + ((size_t)b * S_LEN + qg) * rowStride + (size_t)h * HD;

    // load q row into registers, pre-scaled by 1/sqrt(D), packed f32x2
    const float scale = 0.125f;  // 1/sqrt(64)
    unsigned long long q2[HD / 2];
#pragma unroll
    for (int i = 0; i < HD / 4; i++) {
        float4 v4 = reinterpret_cast<const float4*>(qptr)[i];
        q2[2 * i]     = pack2(v4.x * scale, v4.y * scale);
        q2[2 * i + 1] = pack2(v4.z * scale, v4.w * scale);
    }

    unsigned long long acc[HD / 2];
#pragma unroll
    for (int i = 0; i < HD / 2; i++) acc[i] = 0ull;  // bits(0,0) == (0.f,0.f)
    float m = -__int_as_float(0x7f800000);  // -inf
    float l = 0.0f;

    const int n_ktiles = (qtile * BR + BR) / BC;  // = 2*qtile + 2
    const float* kbase = K + (size_t)b * S_LEN * rowStride + (size_t)h * HD;
    const float* vbase = V + (size_t)b * S_LEN * rowStride + (size_t)h * HD;

    for (int j = 0; j < n_ktiles; j++) {
        const int k0 = j * BC;
        __syncthreads();  // previous tile's compute done before overwrite
        // cooperative coalesced load of K,V tile: BC*HD floats = 1024 float4
#pragma unroll
        for (int i = 0; i < (BC * HD / 4) / BR; i++) {
            int idx = t + i * BR;       // 0..1023
            int row = idx >> 4;         // 16 float4 per row
            int c4 = idx & 15;
            const float4* kg4 = reinterpret_cast<const float4*>(
                kbase + (size_t)(k0 + row) * rowStride);
            const float4* vg4 = reinterpret_cast<const float4*>(
                vbase + (size_t)(k0 + row) * rowStride);
            reinterpret_cast<float4*>(&sK[row][0])[c4] = kg4[c4];
            reinterpret_cast<float4*>(&sV[row][0])[c4] = vg4[c4];
        }
        __syncthreads();

        // causal: number of valid keys in this tile for this row
        int kmax = qg - k0 + 1;
        if (kmax > BC) kmax = BC;

        for (int kk = 0; kk < kmax; kk++) {
            // s = q . k[kk]  (warp-uniform smem reads -> broadcast)
            const ulonglong2* krow =
                reinterpret_cast<const ulonglong2*>(&sK[kk][0]);
            unsigned long long s0 = 0ull, s1 = 0ull, s2 = 0ull, s3 = 0ull;
#pragma unroll
            for (int i = 0; i < HD / 8; i += 2) {
                ulonglong2 ka = krow[i];
                ulonglong2 kb2 = krow[i + 1];
                s0 = fma2(q2[2 * i],     ka.x,  s0);
                s1 = fma2(q2[2 * i + 1], ka.y,  s1);
                s2 = fma2(q2[2 * i + 2], kb2.x, s2);
                s3 = fma2(q2[2 * i + 3], kb2.y, s3);
            }
            // second half
#pragma unroll
            for (int i = HD / 8; i < HD / 4; i += 2) {
                ulonglong2 ka = krow[i];
                ulonglong2 kb2 = krow[i + 1];
                s0 = fma2(q2[2 * i],     ka.x,  s0);
                s1 = fma2(q2[2 * i + 1], ka.y,  s1);
                s2 = fma2(q2[2 * i + 2], kb2.x, s2);
                s3 = fma2(q2[2 * i + 3], kb2.y, s3);
            }
            float2 a0 = unpack2(s0), a1 = unpack2(s1);
            float2 a2 = unpack2(s2), a3 = unpack2(s3);
            float s = ((a0.x + a0.y) + (a1.x + a1.y)) +
                      ((a2.x + a2.y) + (a3.x + a3.y));

            // online softmax (rescale only on max update — rare)
            float p;
            if (s > m) {
                float alpha = __expf(m - s);  // exp(-inf)=0 on first key
                m = s;
                l = l * alpha + 1.0f;
                unsigned long long al2 = pack2(alpha, alpha);
#pragma unroll
                for (int i = 0; i < HD / 2; i++) acc[i] = mul2(acc[i], al2);
                p = 1.0f;
            } else {
                p = __expf(s - m);
                l += p;
            }

            unsigned long long p2 = pack2(p, p);
            const ulonglong2* vrow =
                reinterpret_cast<const ulonglong2*>(&sV[kk][0]);
#pragma unroll
            for (int i = 0; i < HD / 4; i++) {
                ulonglong2 vv = vrow[i];
                acc[2 * i]     = fma2(p2, vv.x, acc[2 * i]);
                acc[2 * i + 1] = fma2(p2, vv.y, acc[2 * i + 1]);
            }
        }
    }

    // normalize and write out (every row has >=1 key, l >= 1)
    float inv_l = 1.0f / l;
    float* optr = O + ((size_t)b * S_LEN + qg) * rowStride + (size_t)h * HD;
#pragma unroll
    for (int i = 0; i < HD / 4; i++) {
        float2 lo = unpack2(acc[2 * i]);
        float2 hi = unpack2(acc[2 * i + 1]);
        float4 o4 = make_float4(lo.x * inv_l, lo.y * inv_l,
                                hi.x * inv_l, hi.y * inv_l);
        reinterpret_cast<float4*>(optr)[i] = o4;
    }
}

extern "C" void kernel_launch(void* const* d_in, const int* in_sizes, int n_in,
                              void* d_out, int out_size) {
    const float* Q = (const float*)d_in[0];
    const float* K = (const float*)d_in[1];
    const float* V = (const float*)d_in[2];
    float* O = (float*)d_out;

    int B = in_sizes[0] / (S_LEN * NHEAD * HD);  // = 2
    dim3 grid(S_LEN / BR, NHEAD, B);
    ring_attn_fwd<<<grid, BR>>>(Q, K, V, O);
}

// round 3
// speedup vs baseline: 5.8529x; 5.8529x over previous
#include <cuda_runtime.h>
#include <cstdint>

// Exact causal attention. B=2, S=8192, H=16, D=64, fp32 in/out.
// Portable-PTX tensor path: mma.sync.m16n8k8 tf32 (sm_80+ base ISA; the harness
// compiles via compute_103 (no 'a'), so tcgen05/TMEM is unavailable).
//
// Per CTA: 128 q rows, 4 warps x 32 rows. K/V tiles of 64 keys, double-buffered
// in SMEM (rows padded to 68 floats -> conflict-free fragment loads), cp.async.
// Q lives in registers as tf32 A-fragments. S in C-fragments; online softmax in
// registers (exp2 domain); C->A fragment conversion for P via shuffles; MMA2
// accumulates into O fragments.

#define S_LEN 8192
#define NHEAD 16
#define HD    64
#define QT    128
#define KT    64
#define NTHR  128
#define KPAD  68                   // floats per padded SMEM row
#define ROWB  (KPAD * 4)           // 272 bytes
#define TILEB (KT * ROWB)          // 17408 bytes per tile
#define KOFF(buf) ((uint32_t)(buf) * TILEB)
#define VOFF(buf) (2u * TILEB + (uint32_t)(buf) * TILEB)
#define SMEM_BYTES (4u * TILEB)    // 69632

static __device__ __forceinline__ float ldsf(uint32_t a) {
    float v; asm volatile("ld.shared.f32 %0, [%1];" : "=f"(v) : "r"(a)); return v;
}
static __device__ __forceinline__ void cp16(uint32_t dst, const void* src) {
    asm volatile("cp.async.cg.shared.global [%0], [%1], 16;" :: "r"(dst), "l"(src) : "memory");
}
static __device__ __forceinline__ float cvt_tf32(float x) {
    float r; asm("cvt.rna.tf32.f32 %0, %1;" : "=f"(r) : "f"(x)); return r;
}
static __device__ __forceinline__ float ex2f(float x) {
    float r; asm("ex2.approx.f32 %0, %1;" : "=f"(r) : "f"(x)); return r;
}
// D += A * B  (m16n8k8, tf32 in, f32 acc)
static __device__ __forceinline__ void mma8(float* c, const uint32_t* a,
                                            uint32_t b0, uint32_t b1) {
    asm volatile(
        "mma.sync.aligned.m16n8k8.row.col.f32.tf32.tf32.f32 "
        "{%0,%1,%2,%3}, {%4,%5,%6,%7}, {%8,%9}, {%0,%1,%2,%3};"
        : "+f"(c[0]), "+f"(c[1]), "+f"(c[2]), "+f"(c[3])
        : "r"(a[0]), "r"(a[1]), "r"(a[2]), "r"(a[3]), "r"(b0), "r"(b1));
}

// cooperative cp.async of K and V tile j into buffer buf
static __device__ __forceinline__ void prefetch_kv(
    int t, int j, int buf, uint32_t sb,
    const float* __restrict__ Kb, const float* __restrict__ Vb)
{
    const size_t str = (size_t)NHEAD * HD;  // 1024 floats
    const float* kt = Kb + (size_t)(j * KT) * str;
    const float* vt = Vb + (size_t)(j * KT) * str;
    const uint32_t kd = sb + KOFF(buf);
    const uint32_t vd = sb + VOFF(buf);
#pragma unroll
    for (int n = 0; n < 8; n++) {
        int i = t + n * NTHR;           // 0..1023
        int row = i >> 4, c4 = i & 15;  // 16 float4 per 64-float row
        uint32_t off = (uint32_t)row * ROWB + (uint32_t)c4 * 16u;
        cp16(kd + off, kt + (size_t)row * str + c4 * 4);
        cp16(vd + off, vt + (size_t)row * str + c4 * 4);
    }
    asm volatile("cp.async.commit_group;" ::: "memory");
}

__global__ void __launch_bounds__(NTHR, 2) fa_mma_tf32(
    const float* __restrict__ Q, const float* __restrict__ K,
    const float* __restrict__ V, float* __restrict__ Ogm)
{
    extern __shared__ __align__(16) char smem_raw[];
    const uint32_t sb = (uint32_t)__cvta_generic_to_shared(smem_raw);

    const int t = threadIdx.x, lane = t & 31, w = t >> 5;
    const int qt = (int)gridDim.x - 1 - (int)blockIdx.x;  // heavy tiles first
    const int h = blockIdx.y, b = blockIdx.z;
    const size_t str = (size_t)NHEAD * HD;

    const float* Qb = Q + ((size_t)b * S_LEN) * str + (size_t)h * HD;
    const float* Kb = K + ((size_t)b * S_LEN) * str + (size_t)h * HD;
    const float* Vb = V + ((size_t)b * S_LEN) * str + (size_t)h * HD;

    const int qbase = qt * QT + w * 32;      // first q row of this warp
    const int g = lane >> 2;                 // row group within fragment
    const int c4l = lane & 3;

    // ---- load Q into tf32 A-fragments: qf[mt][k][4] ----
    // a0=(g, c) a1=(g+8, c) a2=(g, c+4) a3=(g+8, c+4); c = k*8 + lane%4
    const float QS = 0.125f * 1.44269504088896f;  // 1/sqrt(64) * log2(e)
    uint32_t qf[2][8][4];
#pragma unroll
    for (int mt = 0; mt < 2; mt++) {
        const float* q0 = Qb + (size_t)(qbase + mt * 16 + g) * str;
        const float* q1 = q0 + 8 * str;
#pragma unroll
        for (int k = 0; k < 8; k++) {
            int c = k * 8 + c4l;
            qf[mt][k][0] = __float_as_uint(cvt_tf32(q0[c] * QS));
            qf[mt][k][1] = __float_as_uint(cvt_tf32(q1[c] * QS));
            qf[mt][k][2] = __float_as_uint(cvt_tf32(q0[c + 4] * QS));
            qf[mt][k][3] = __float_as_uint(cvt_tf32(q1[c + 4] * QS));
        }
    }

    float of[2][8][4];
#pragma unroll
    for (int mt = 0; mt < 2; mt++)
#pragma unroll
        for (int n = 0; n < 8; n++)
#pragma unroll
            for (int r = 0; r < 4; r++) of[mt][n][r] = 0.0f;

    float m_s[2][2], l_s[2][2];
#pragma unroll
    for (int i = 0; i < 2; i++) {
        m_s[i][0] = m_s[i][1] = -1e30f;
        l_s[i][0] = l_s[i][1] = 0.0f;
    }

    const int ntiles = 2 * qt + 2;
    prefetch_kv(t, 0, 0, sb, Kb, Vb);

    // fragment-load lane bases
    const uint32_t kb_lane = (uint32_t)g * ROWB + (uint32_t)c4l * 4u;   // MMA1 B
    const uint32_t vb_lane = (uint32_t)c4l * ROWB + (uint32_t)g * 4u;   // MMA2 B
    const int s0 = (lane & 28) | ((lane & 3) >> 1);
    const int s1 = s0 + 2;
    const bool oddl = (lane & 1);

    for (int j = 0; j < ntiles; j++) {
        const int buf = j & 1;
        if (j + 1 < ntiles) {
            prefetch_kv(t, j + 1, buf ^ 1, sb, Kb, Vb);
            asm volatile("cp.async.wait_group 1;" ::: "memory");
        } else {
            asm volatile("cp.async.wait_group 0;" ::: "memory");
        }
        __syncthreads();

        const int j64 = j * KT;
        if (j64 <= qbase + 31) {  // not fully masked for this warp
            // ---- MMA1: S = Q * K^T ----
            float sf[2][8][4];
#pragma unroll
            for (int mt = 0; mt < 2; mt++)
#pragma unroll
                for (int n = 0; n < 8; n++)
#pragma unroll
                    for (int r = 0; r < 4; r++) sf[mt][n][r] = 0.0f;

            const uint32_t kbase = sb + KOFF(buf) + kb_lane;
#pragma unroll
            for (int k = 0; k < 8; k++) {
#pragma unroll
                for (int n = 0; n < 8; n++) {
                    uint32_t a = kbase + (uint32_t)n * (8u * ROWB) + (uint32_t)k * 32u;
                    uint32_t b0 = __float_as_uint(ldsf(a));
                    uint32_t b1 = __float_as_uint(ldsf(a + 16u));
                    mma8(sf[0][n], qf[0][k], b0, b1);
                    mma8(sf[1][n], qf[1][k], b0, b1);
                }
            }

            // ---- causal mask (diagonal tiles only) ----
            if (j64 + KT - 1 > qbase) {
#pragma unroll
                for (int mt = 0; mt < 2; mt++) {
                    int r0 = qbase + mt * 16 + g;
#pragma unroll
                    for (int n = 0; n < 8; n++) {
                        int kcol = j64 + n * 8 + 2 * c4l;
                        if (kcol > r0)     sf[mt][n][0] = -1e30f;
                        if (kcol + 1 > r0) sf[mt][n][1] = -1e30f;
                        if (kcol > r0 + 8)     sf[mt][n][2] = -1e30f;
                        if (kcol + 1 > r0 + 8) sf[mt][n][3] = -1e30f;
                    }
                }
            }

            // ---- online softmax (exp2 domain), per (mt, rowhalf) ----
            float alpha[2][2];
#pragma unroll
            for (int mt = 0; mt < 2; mt++) {
#pragma unroll
                for (int hf = 0; hf < 2; hf++) {
                    float mx = -1e30f;
#pragma unroll
                    for (int n = 0; n < 8; n++)
                        mx = fmaxf(mx, fmaxf(sf[mt][n][2 * hf], sf[mt][n][2 * hf + 1]));
                    mx = fmaxf(mx, __shfl_xor_sync(0xffffffffu, mx, 1));
                    mx = fmaxf(mx, __shfl_xor_sync(0xffffffffu, mx, 2));
                    float mn = fmaxf(m_s[mt][hf], mx);
                    float al = ex2f(m_s[mt][hf] - mn);
                    float sum = 0.0f;
#pragma unroll
                    for (int n = 0; n < 8; n++) {
                        float p0 = cvt_tf32(ex2f(sf[mt][n][2 * hf] - mn));
                        float p1 = cvt_tf32(ex2f(sf[mt][n][2 * hf + 1] - mn));
                        sf[mt][n][2 * hf] = p0;
                        sf[mt][n][2 * hf + 1] = p1;
                        sum += p0 + p1;
                    }
                    sum += __shfl_xor_sync(0xffffffffu, sum, 1);
                    sum += __shfl_xor_sync(0xffffffffu, sum, 2);
                    l_s[mt][hf] = l_s[mt][hf] * al + sum;
                    m_s[mt][hf] = mn;
                    alpha[mt][hf] = al;
                }
            }
            // rescale O
#pragma unroll
            for (int mt = 0; mt < 2; mt++)
#pragma unroll
                for (int n = 0; n < 8; n++) {
                    of[mt][n][0] *= alpha[mt][0];
                    of[mt][n][1] *= alpha[mt][0];
                    of[mt][n][2] *= alpha[mt][1];
                    of[mt][n][3] *= alpha[mt][1];
                }

            // ---- MMA2: O += P * V ----
            const uint32_t vbase = sb + VOFF(buf) + vb_lane;
#pragma unroll
            for (int kk = 0; kk < 8; kk++) {
                uint32_t af[2][4];
#pragma unroll
                for (int mt = 0; mt < 2; mt++) {
                    float x00 = __shfl_sync(0xffffffffu, sf[mt][kk][0], s0);
                    float x01 = __shfl_sync(0xffffffffu, sf[mt][kk][1], s0);
                    float y00 = __shfl_sync(0xffffffffu, sf[mt][kk][0], s1);
                    float y01 = __shfl_sync(0xffffffffu, sf[mt][kk][1], s1);
                    float x10 = __shfl_sync(0xffffffffu, sf[mt][kk][2], s0);
                    float x11 = __shfl_sync(0xffffffffu, sf[mt][kk][3], s0);
                    float y10 = __shfl_sync(0xffffffffu, sf[mt][kk][2], s1);
                    float y11 = __shfl_sync(0xffffffffu, sf[mt][kk][3], s1);
                    af[mt][0] = __float_as_uint(oddl ? x01 : x00);
                    af[mt][2] = __float_as_uint(oddl ? y01 : y00);
                    af[mt][1] = __float_as_uint(oddl ? x11 : x10);
                    af[mt][3] = __float_as_uint(oddl ? y11 : y10);
                }
#pragma unroll
                for (int n = 0; n < 8; n++) {
                    uint32_t a = vbase + (uint32_t)kk * (8u * ROWB) + (uint32_t)n * 32u;
                    uint32_t b0 = __float_as_uint(ldsf(a));
                    uint32_t b1 = __float_as_uint(ldsf(a + 4u * ROWB));
                    mma8(of[0][n], af[0], b0, b1);
                    mma8(of[1][n], af[1], b0, b1);
                }
            }
        }
        __syncthreads();
    }

    // ---- epilogue ----
    float inv[2][2];
#pragma unroll
    for (int mt = 0; mt < 2; mt++) {
        inv[mt][0] = 1.0f / l_s[mt][0];
        inv[mt][1] = 1.0f / l_s[mt][1];
    }
    float* Ob = Ogm + ((size_t)b * S_LEN) * str + (size_t)h * HD;
#pragma unroll
    for (int mt = 0; mt < 2; mt++) {
        float* o0 = Ob + (size_t)(qbase + mt * 16 + g) * str;
        float* o1 = o0 + 8 * str;
#pragma unroll
        for (int n = 0; n < 8; n++) {
            int d0 = n * 8 + 2 * c4l;
            float2 v0 = make_float2(of[mt][n][0] * inv[mt][0],
                                    of[mt][n][1] * inv[mt][0]);
            float2 v1 = make_float2(of[mt][n][2] * inv[mt][1],
                                    of[mt][n][3] * inv[mt][1]);
            *(float2*)(o0 + d0) = v0;
            *(float2*)(o1 + d0) = v1;
        }
    }
}

extern "C" void kernel_launch(void* const* d_in, const int* in_sizes, int n_in,
                              void* d_out, int out_size) {
    const float* Q = (const float*)d_in[0];
    const float* K = (const float*)d_in[1];
    const float* V = (const float*)d_in[2];
    float* O = (float*)d_out;

    int B = in_sizes[0] / (S_LEN * NHEAD * HD);  // = 2
    cudaFuncSetAttribute(fa_mma_tf32, cudaFuncAttributeMaxDynamicSharedMemorySize, SMEM_BYTES);
    dim3 grid(S_LEN / QT, NHEAD, B);
    fa_mma_tf32<<<grid, NTHR, SMEM_BYTES>>>(Q, K, V, O);
}

// round 4
// speedup vs baseline: 13.9025x; 2.3753x over previous
#include <cuda_runtime.h>
#include <cuda_fp16.h>
#include <cstdint>

// Exact causal attention. B=2, S=8192, H=16, D=64, fp32 in/out.
// fp16 mma.m16n8k16 flash attention (base ISA; compute_103 has no tcgen05).
// Pre-pass converts K -> fp16 [bh][s][d], V -> fp16 transposed [bh][d][s].
// Main kernel: 128 q rows/CTA, 4 warps x 32 rows, KT=64 key tiles double-
// buffered via cp.async. MMA1 C-fragment feeds MMA2 A-fragment directly
// (no shuffles). Online softmax in exp2 domain.

#define S_LEN 8192
#define NHEAD 16
#define HD    64
#define QT    128
#define KT    64
#define NTHR  128
#define ROWB  144u                 // 128B fp16 row + 16B pad (conflict-free)
#define TILEB (64u * ROWB)         // 9216 B
#define KOFF(buf) ((uint32_t)(buf) * 2u * TILEB)
#define VOFF(buf) ((uint32_t)(buf) * 2u * TILEB + TILEB)
#define SMEM_BYTES (4u * TILEB)    // 36864

__device__ __align__(16) static __half Khg[(size_t)2 * NHEAD * S_LEN * HD];
__device__ __align__(16) static __half Vtg[(size_t)2 * NHEAD * HD * S_LEN];

static __device__ __forceinline__ float ldsf(uint32_t a) {
    float v; asm volatile("ld.shared.f32 %0, [%1];" : "=f"(v) : "r"(a)); return v;
}
static __device__ __forceinline__ void cp16(uint32_t dst, const void* src) {
    asm volatile("cp.async.cg.shared.global [%0], [%1], 16;" :: "r"(dst), "l"(src) : "memory");
}
static __device__ __forceinline__ float ex2f(float x) {
    float r; asm("ex2.approx.f32 %0, %1;" : "=f"(r) : "f"(x)); return r;
}
static __device__ __forceinline__ uint32_t packh2(float lo, float hi) {
    __half2 h = __floats2half2_rn(lo, hi);
    return *reinterpret_cast<uint32_t*>(&h);
}
// D += A * B  (m16n8k16, fp16 in, f32 acc)
static __device__ __forceinline__ void mma16(float* c, const uint32_t* a,
                                             uint32_t b0, uint32_t b1) {
    asm volatile(
        "mma.sync.aligned.m16n8k16.row.col.f32.f16.f16.f32 "
        "{%0,%1,%2,%3}, {%4,%5,%6,%7}, {%8,%9}, {%0,%1,%2,%3};"
        : "+f"(c[0]), "+f"(c[1]), "+f"(c[2]), "+f"(c[3])
        : "r"(a[0]), "r"(a[1]), "r"(a[2]), "r"(a[3]), "r"(b0), "r"(b1));
}

// ---------------- pre-pass: K -> fp16 [bh][s][d]; V -> fp16^T [bh][d][s] ----
__global__ void __launch_bounds__(128) convert_kv(
    const float* __restrict__ K, const float* __restrict__ V)
{
    __shared__ __half sv[64][68];
    const int st = blockIdx.x, h = blockIdx.y, b = blockIdx.z, t = threadIdx.x;
    const int bh = b * NHEAD + h;
    const int sl = t >> 1, dh = (t & 1) * 32;
    const size_t goff = ((size_t)(b * S_LEN + st * 64 + sl)) * (NHEAD * HD)
                        + (size_t)h * HD + dh;
    const float4* k4 = (const float4*)(K + goff);
    const float4* v4 = (const float4*)(V + goff);
    uint32_t kk[16];
#pragma unroll
    for (int i = 0; i < 8; i++) {
        float4 a = k4[i];
        kk[2 * i]     = packh2(a.x, a.y);
        kk[2 * i + 1] = packh2(a.z, a.w);
    }
    uint4* kd = (uint4*)(Khg + ((size_t)bh * S_LEN + st * 64 + sl) * HD + dh);
#pragma unroll
    for (int i = 0; i < 4; i++) kd[i] = ((uint4*)kk)[i];

    uint32_t* svr = (uint32_t*)&sv[sl][dh];
#pragma unroll
    for (int i = 0; i < 8; i++) {
        float4 a = v4[i];
        svr[2 * i]     = packh2(a.x, a.y);
        svr[2 * i + 1] = packh2(a.z, a.w);
    }
    __syncthreads();
    const int d = t >> 1, s0 = (t & 1) * 32;
    uint32_t ov[16];
#pragma unroll
    for (int i = 0; i < 16; i++) {
        __half2 p = __halves2half2(sv[s0 + 2 * i][d], sv[s0 + 2 * i + 1][d]);
        ov[i] = *reinterpret_cast<uint32_t*>(&p);
    }
    uint4* vd = (uint4*)(Vtg + ((size_t)bh * HD + d) * S_LEN + st * 64 + s0);
#pragma unroll
    for (int i = 0; i < 4; i++) vd[i] = ((uint4*)ov)[i];
}

// ---------------- main kernel ----------------
static __device__ __forceinline__ void prefetch_kv(
    int t, int j, int buf, uint32_t sb,
    const __half* __restrict__ Ks, const __half* __restrict__ Vs)
{
#pragma unroll
    for (int n = 0; n < 4; n++) {
        int idx = t + n * NTHR;        // 0..511
        int row = idx >> 3, seg = idx & 7;
        uint32_t off = (uint32_t)row * ROWB + (uint32_t)seg * 16u;
        cp16(sb + KOFF(buf) + off, Ks + (size_t)(j * KT + row) * HD + seg * 8);
        cp16(sb + VOFF(buf) + off, Vs + (size_t)row * S_LEN + j * KT + seg * 8);
    }
    asm volatile("cp.async.commit_group;" ::: "memory");
}

__global__ void __launch_bounds__(NTHR, 2) fa_mma_f16(
    const float* __restrict__ Q, float* __restrict__ Ogm)
{
    extern __shared__ __align__(16) char smem_raw[];
    const uint32_t sb = (uint32_t)__cvta_generic_to_shared(smem_raw);

    const int t = threadIdx.x, lane = t & 31, w = t >> 5;
    const int qt = (int)gridDim.x - 1 - (int)blockIdx.x;  // heavy tiles first
    const int h = blockIdx.y, b = blockIdx.z;
    const int bh = b * NHEAD + h;
    const size_t str = (size_t)NHEAD * HD;

    const float*  Qb = Q + ((size_t)b * S_LEN) * str + (size_t)h * HD;
    const __half* Ks = Khg + (size_t)bh * S_LEN * HD;
    const __half* Vs = Vtg + (size_t)bh * HD * S_LEN;

    const int qbase = qt * QT + w * 32;
    const int g = lane >> 2;
    const int c4l = lane & 3;

    // Q -> fp16 A-fragments (scale*log2e folded): qf[mt][kblk][4]
    const float QS = 0.125f * 1.44269504088896f;
    uint32_t qf[2][4][4];
#pragma unroll
    for (int mt = 0; mt < 2; mt++) {
        const float* q0 = Qb + (size_t)(qbase + mt * 16 + g) * str;
        const float* q1 = q0 + 8 * str;
#pragma unroll
        for (int kb = 0; kb < 4; kb++) {
            int c = kb * 16 + 2 * c4l;
            qf[mt][kb][0] = packh2(q0[c] * QS,     q0[c + 1] * QS);
            qf[mt][kb][1] = packh2(q1[c] * QS,     q1[c + 1] * QS);
            qf[mt][kb][2] = packh2(q0[c + 8] * QS, q0[c + 9] * QS);
            qf[mt][kb][3] = packh2(q1[c + 8] * QS, q1[c + 9] * QS);
        }
    }

    float of[2][8][4];
#pragma unroll
    for (int mt = 0; mt < 2; mt++)
#pragma unroll
        for (int n = 0; n < 8; n++)
#pragma unroll
            for (int r = 0; r < 4; r++) of[mt][n][r] = 0.0f;

    float m_s[2][2], l_s[2][2];
#pragma unroll
    for (int i = 0; i < 2; i++) {
        m_s[i][0] = m_s[i][1] = -1e30f;
        l_s[i][0] = l_s[i][1] = 0.0f;
    }

    const int ntiles = 2 * qt + 2;
    prefetch_kv(t, 0, 0, sb, Ks, Vs);

    const uint32_t frag_lane = (uint32_t)g * ROWB + (uint32_t)c4l * 4u;

    for (int j = 0; j < ntiles; j++) {
        const int buf = j & 1;
        if (j + 1 < ntiles) {
            prefetch_kv(t, j + 1, buf ^ 1, sb, Ks, Vs);
            asm volatile("cp.async.wait_group 1;" ::: "memory");
        } else {
            asm volatile("cp.async.wait_group 0;" ::: "memory");
        }
        __syncthreads();

        const int j64 = j * KT;
        if (j64 <= qbase + 31) {
            // ---- MMA1: S = Q * K^T ----
            float sf[2][8][4];
#pragma unroll
            for (int mt = 0; mt < 2; mt++)
#pragma unroll
                for (int n = 0; n < 8; n++)
#pragma unroll
                    for (int r = 0; r < 4; r++) sf[mt][n][r] = 0.0f;

            const uint32_t kbase = sb + KOFF(buf) + frag_lane;
#pragma unroll
            for (int n = 0; n < 8; n++) {
#pragma unroll
                for (int kb = 0; kb < 4; kb++) {
                    uint32_t a = kbase + (uint32_t)n * (8u * ROWB) + (uint32_t)kb * 32u;
                    uint32_t b0 = __float_as_uint(ldsf(a));
                    uint32_t b1 = __float_as_uint(ldsf(a + 16u));
                    mma16(sf[0][n], qf[0][kb], b0, b1);
                    mma16(sf[1][n], qf[1][kb], b0, b1);
                }
            }

            // ---- causal mask (diagonal tiles only) ----
            if (j64 + KT - 1 > qbase) {
#pragma unroll
                for (int mt = 0; mt < 2; mt++) {
                    int r0 = qbase + mt * 16 + g;
#pragma unroll
                    for (int n = 0; n < 8; n++) {
                        int kcol = j64 + n * 8 + 2 * c4l;
                        if (kcol > r0)         sf[mt][n][0] = -1e30f;
                        if (kcol + 1 > r0)     sf[mt][n][1] = -1e30f;
                        if (kcol > r0 + 8)     sf[mt][n][2] = -1e30f;
                        if (kcol + 1 > r0 + 8) sf[mt][n][3] = -1e30f;
                    }
                }
            }

            // ---- online softmax (exp2 domain) ----
            float alpha[2][2];
#pragma unroll
            for (int mt = 0; mt < 2; mt++) {
#pragma unroll
                for (int hf = 0; hf < 2; hf++) {
                    float mx = -1e30f;
#pragma unroll
                    for (int n = 0; n < 8; n++)
                        mx = fmaxf(mx, fmaxf(sf[mt][n][2 * hf], sf[mt][n][2 * hf + 1]));
                    mx = fmaxf(mx, __shfl_xor_sync(0xffffffffu, mx, 1));
                    mx = fmaxf(mx, __shfl_xor_sync(0xffffffffu, mx, 2));
                    float mn = fmaxf(m_s[mt][hf], mx);
                    float al = ex2f(m_s[mt][hf] - mn);
                    float sum = 0.0f;
#pragma unroll
                    for (int n = 0; n < 8; n++) {
                        float p0 = ex2f(sf[mt][n][2 * hf] - mn);
                        float p1 = ex2f(sf[mt][n][2 * hf + 1] - mn);
                        sf[mt][n][2 * hf] = p0;
                        sf[mt][n][2 * hf + 1] = p1;
                        sum += p0 + p1;
                    }
                    sum += __shfl_xor_sync(0xffffffffu, sum, 1);
                    sum += __shfl_xor_sync(0xffffffffu, sum, 2);
                    l_s[mt][hf] = l_s[mt][hf] * al + sum;
                    m_s[mt][hf] = mn;
                    alpha[mt][hf] = al;
                }
            }

            // pack P to fp16 (MMA1 C-frag == MMA2 A-frag layout: no shuffles)
            uint32_t ph[2][8][2];
#pragma unroll
            for (int mt = 0; mt < 2; mt++)
#pragma unroll
                for (int n = 0; n < 8; n++) {
                    ph[mt][n][0] = packh2(sf[mt][n][0], sf[mt][n][1]);
                    ph[mt][n][1] = packh2(sf[mt][n][2], sf[mt][n][3]);
                }

            // rescale O
#pragma unroll
            for (int mt = 0; mt < 2; mt++)
#pragma unroll
                for (int n = 0; n < 8; n++) {
                    of[mt][n][0] *= alpha[mt][0];
                    of[mt][n][1] *= alpha[mt][0];
                    of[mt][n][2] *= alpha[mt][1];
                    of[mt][n][3] *= alpha[mt][1];
                }

            // ---- MMA2: O += P * V ----
            const uint32_t vbase = sb + VOFF(buf) + frag_lane;
#pragma unroll
            for (int kk = 0; kk < 4; kk++) {
                uint32_t af0[4] = { ph[0][2 * kk][0], ph[0][2 * kk][1],
                                    ph[0][2 * kk + 1][0], ph[0][2 * kk + 1][1] };
                uint32_t af1[4] = { ph[1][2 * kk][0], ph[1][2 * kk][1],
                                    ph[1][2 * kk + 1][0], ph[1][2 * kk + 1][1] };
#pragma unroll
                for (int n = 0; n < 8; n++) {
                    uint32_t a = vbase + (uint32_t)n * (8u * ROWB) + (uint32_t)kk * 32u;
                    uint32_t b0 = __float_as_uint(ldsf(a));
                    uint32_t b1 = __float_as_uint(ldsf(a + 16u));
                    mma16(of[0][n], af0, b0, b1);
                    mma16(of[1][n], af1, b0, b1);
                }
            }
        }
        __syncthreads();
    }

    // ---- epilogue ----
    float inv[2][2];
#pragma unroll
    for (int mt = 0; mt < 2; mt++) {
        inv[mt][0] = 1.0f / l_s[mt][0];
        inv[mt][1] = 1.0f / l_s[mt][1];
    }
    float* Ob = Ogm + ((size_t)b * S_LEN) * str + (size_t)h * HD;
#pragma unroll
    for (int mt = 0; mt < 2; mt++) {
        float* o0 = Ob + (size_t)(qbase + mt * 16 + g) * str;
        float* o1 = o0 + 8 * str;
#pragma unroll
        for (int n = 0; n < 8; n++) {
            int d0 = n * 8 + 2 * c4l;
            *(float2*)(o0 + d0) = make_float2(of[mt][n][0] * inv[mt][0],
                                              of[mt][n][1] * inv[mt][0]);
            *(float2*)(o1 + d0) = make_float2(of[mt][n][2] * inv[mt][1],
                                              of[mt][n][3] * inv[mt][1]);
        }
    }
}

extern "C" void kernel_launch(void* const* d_in, const int* in_sizes, int n_in,
                              void* d_out, int out_size) {
    const float* Q = (const float*)d_in[0];
    const float* K = (const float*)d_in[1];
    const float* V = (const float*)d_in[2];
    float* O = (float*)d_out;

    int B = in_sizes[0] / (S_LEN * NHEAD * HD);  // = 2

    dim3 cgrid(S_LEN / 64, NHEAD, B);
    convert_kv<<<cgrid, 128>>>(K, V);

    cudaFuncSetAttribute(fa_mma_f16, cudaFuncAttributeMaxDynamicSharedMemorySize, SMEM_BYTES);
    dim3 grid(S_LEN / QT, NHEAD, B);
    fa_mma_f16<<<grid, NTHR, SMEM_BYTES>>>(Q, O);
}

// round 5
// speedup vs baseline: 14.8591x; 1.0688x over previous
#include <cuda_runtime.h>
#include <cuda_fp16.h>
#include <cstdint>

// Exact causal attention. B=2, S=8192, H=16, D=64, fp32 in/out.
// fp16 mma.m16n8k16 flash attention. R5: ldmatrix.x4 B-fragments, f16x2 exp,
// row-sum l computed by a ones-column MMA (fp32 accum of fp16 P).

#define S_LEN 8192
#define NHEAD 16
#define HD    64
#define QT    128
#define KT    64
#define NTHR  128
#define ROWB  144u                 // 128B fp16 row + 16B pad
#define TILEB (64u * ROWB)         // 9216 B
#define KOFF(buf) ((uint32_t)(buf) * 2u * TILEB)
#define VOFF(buf) ((uint32_t)(buf) * 2u * TILEB + TILEB)
#define SMEM_BYTES (4u * TILEB)    // 36864
#define ONES2 0x3C003C00u          // half2(1.0, 1.0)

__device__ __align__(16) static __half Khg[(size_t)2 * NHEAD * S_LEN * HD];
__device__ __align__(16) static __half Vtg[(size_t)2 * NHEAD * HD * S_LEN];

static __device__ __forceinline__ void cp16(uint32_t dst, const void* src) {
    asm volatile("cp.async.cg.shared.global [%0], [%1], 16;" :: "r"(dst), "l"(src) : "memory");
}
static __device__ __forceinline__ float ex2f(float x) {
    float r; asm("ex2.approx.f32 %0, %1;" : "=f"(r) : "f"(x)); return r;
}
static __device__ __forceinline__ uint32_t h2ex2(uint32_t x) {
    uint32_t r; asm("ex2.approx.f16x2 %0, %1;" : "=r"(r) : "r"(x)); return r;
}
static __device__ __forceinline__ uint32_t packh2(float lo, float hi) {
    __half2 h = __floats2half2_rn(lo, hi);
    return *reinterpret_cast<uint32_t*>(&h);
}
static __device__ __forceinline__ void ldsm4(uint32_t* r, uint32_t addr) {
    asm volatile("ldmatrix.sync.aligned.m8n8.x4.shared.b16 {%0,%1,%2,%3}, [%4];"
                 : "=r"(r[0]), "=r"(r[1]), "=r"(r[2]), "=r"(r[3]) : "r"(addr));
}
// D += A * B  (m16n8k16, fp16 in, f32 acc)
static __device__ __forceinline__ void mma16(float* c, const uint32_t* a,
                                             uint32_t b0, uint32_t b1) {
    asm volatile(
        "mma.sync.aligned.m16n8k16.row.col.f32.f16.f16.f32 "
        "{%0,%1,%2,%3}, {%4,%5,%6,%7}, {%8,%9}, {%0,%1,%2,%3};"
        : "+f"(c[0]), "+f"(c[1]), "+f"(c[2]), "+f"(c[3])
        : "r"(a[0]), "r"(a[1]), "r"(a[2]), "r"(a[3]), "r"(b0), "r"(b1));
}

// ---------------- pre-pass: K -> fp16 [bh][s][d]; V -> fp16^T [bh][d][s] ----
__global__ void __launch_bounds__(128) convert_kv(
    const float* __restrict__ K, const float* __restrict__ V)
{
    __shared__ __half sv[64][68];
    const int st = blockIdx.x, h = blockIdx.y, b = blockIdx.z, t = threadIdx.x;
    const int bh = b * NHEAD + h;
    const int sl = t >> 1, dh = (t & 1) * 32;
    const size_t goff = ((size_t)(b * S_LEN + st * 64 + sl)) * (NHEAD * HD)
                        + (size_t)h * HD + dh;
    const float4* k4 = (const float4*)(K + goff);
    const float4* v4 = (const float4*)(V + goff);
    uint32_t kk[16];
#pragma unroll
    for (int i = 0; i < 8; i++) {
        float4 a = k4[i];
        kk[2 * i]     = packh2(a.x, a.y);
        kk[2 * i + 1] = packh2(a.z, a.w);
    }
    uint4* kd = (uint4*)(Khg + ((size_t)bh * S_LEN + st * 64 + sl) * HD + dh);
#pragma unroll
    for (int i = 0; i < 4; i++) kd[i] = ((uint4*)kk)[i];

    uint32_t* svr = (uint32_t*)&sv[sl][dh];
#pragma unroll
    for (int i = 0; i < 8; i++) {
        float4 a = v4[i];
        svr[2 * i]     = packh2(a.x, a.y);
        svr[2 * i + 1] = packh2(a.z, a.w);
    }
    __syncthreads();
    const int d = t >> 1, s0 = (t & 1) * 32;
    uint32_t ov[16];
#pragma unroll
    for (int i = 0; i < 16; i++) {
        __half2 p = __halves2half2(sv[s0 + 2 * i][d], sv[s0 + 2 * i + 1][d]);
        ov[i] = *reinterpret_cast<uint32_t*>(&p);
    }
    uint4* vd = (uint4*)(Vtg + ((size_t)bh * HD + d) * S_LEN + st * 64 + s0);
#pragma unroll
    for (int i = 0; i < 4; i++) vd[i] = ((uint4*)ov)[i];
}

// ---------------- main kernel ----------------
static __device__ __forceinline__ void prefetch_kv(
    int t, int j, int buf, uint32_t sb,
    const __half* __restrict__ Ks, const __half* __restrict__ Vs)
{
#pragma unroll
    for (int n = 0; n < 4; n++) {
        int idx = t + n * NTHR;        // 0..511
        int row = idx >> 3, seg = idx & 7;
        uint32_t off = (uint32_t)row * ROWB + (uint32_t)seg * 16u;
        cp16(sb + KOFF(buf) + off, Ks + (size_t)(j * KT + row) * HD + seg * 8);
        cp16(sb + VOFF(buf) + off, Vs + (size_t)row * S_LEN + j * KT + seg * 8);
    }
    asm volatile("cp.async.commit_group;" ::: "memory");
}

__global__ void __launch_bounds__(NTHR, 2) fa_mma_f16(
    const float* __restrict__ Q, float* __restrict__ Ogm)
{
    extern __shared__ __align__(16) char smem_raw[];
    const uint32_t sb = (uint32_t)__cvta_generic_to_shared(smem_raw);

    const int t = threadIdx.x, lane = t & 31, w = t >> 5;
    const int qt = (int)gridDim.x - 1 - (int)blockIdx.x;  // heavy tiles first
    const int h = blockIdx.y, b = blockIdx.z;
    const int bh = b * NHEAD + h;
    const size_t str = (size_t)NHEAD * HD;

    const float*  Qb = Q + ((size_t)b * S_LEN) * str + (size_t)h * HD;
    const __half* Ks = Khg + (size_t)bh * S_LEN * HD;
    const __half* Vs = Vtg + (size_t)bh * HD * S_LEN;

    const int qbase = qt * QT + w * 32;
    const int g = lane >> 2;
    const int c4l = lane & 3;

    // Q -> fp16 A-fragments (scale*log2e folded): qf[mt][kblk][4]
    const float QS = 0.125f * 1.44269504088896f;
    uint32_t qf[2][4][4];
#pragma unroll
    for (int mt = 0; mt < 2; mt++) {
        const float* q0 = Qb + (size_t)(qbase + mt * 16 + g) * str;
        const float* q1 = q0 + 8 * str;
#pragma unroll
        for (int kb = 0; kb < 4; kb++) {
            int c = kb * 16 + 2 * c4l;
            qf[mt][kb][0] = packh2(q0[c] * QS,     q0[c + 1] * QS);
            qf[mt][kb][1] = packh2(q1[c] * QS,     q1[c + 1] * QS);
            qf[mt][kb][2] = packh2(q0[c + 8] * QS, q0[c + 9] * QS);
            qf[mt][kb][3] = packh2(q1[c + 8] * QS, q1[c + 9] * QS);
        }
    }

    float of[2][8][4];
    float lf[2][4];
#pragma unroll
    for (int mt = 0; mt < 2; mt++) {
#pragma unroll
        for (int n = 0; n < 8; n++)
#pragma unroll
            for (int r = 0; r < 4; r++) of[mt][n][r] = 0.0f;
#pragma unroll
        for (int r = 0; r < 4; r++) lf[mt][r] = 0.0f;
    }
    float m_s[2][2];
#pragma unroll
    for (int i = 0; i < 2; i++) m_s[i][0] = m_s[i][1] = -1e30f;

    const int ntiles = 2 * qt + 2;
    prefetch_kv(t, 0, 0, sb, Ks, Vs);

    // ldmatrix per-lane base: row = lane&7, tile = lane>>3 (16B each)
    const uint32_t lm_lane = (uint32_t)(lane & 7) * ROWB + (uint32_t)(lane >> 3) * 16u;

    for (int j = 0; j < ntiles; j++) {
        const int buf = j & 1;
        if (j + 1 < ntiles) {
            prefetch_kv(t, j + 1, buf ^ 1, sb, Ks, Vs);
            asm volatile("cp.async.wait_group 1;" ::: "memory");
        } else {
            asm volatile("cp.async.wait_group 0;" ::: "memory");
        }
        __syncthreads();

        const int j64 = j * KT;
        if (j64 <= qbase + 31) {
            // ---- MMA1: S = Q * K^T ----
            float sf[2][8][4];
#pragma unroll
            for (int mt = 0; mt < 2; mt++)
#pragma unroll
                for (int n = 0; n < 8; n++)
#pragma unroll
                    for (int r = 0; r < 4; r++) sf[mt][n][r] = 0.0f;

            const uint32_t kbase = sb + KOFF(buf) + lm_lane;
#pragma unroll
            for (int n = 0; n < 8; n++) {
                uint32_t kf[8];
                ldsm4(kf,     kbase + (uint32_t)n * (8u * ROWB));
                ldsm4(kf + 4, kbase + (uint32_t)n * (8u * ROWB) + 64u);
#pragma unroll
                for (int kb = 0; kb < 4; kb++) {
                    mma16(sf[0][n], qf[0][kb], kf[2 * kb], kf[2 * kb + 1]);
                    mma16(sf[1][n], qf[1][kb], kf[2 * kb], kf[2 * kb + 1]);
                }
            }

            // ---- causal mask (diagonal tiles only) ----
            if (j64 + KT - 1 > qbase) {
#pragma unroll
                for (int mt = 0; mt < 2; mt++) {
                    int r0 = qbase + mt * 16 + g;
#pragma unroll
                    for (int n = 0; n < 8; n++) {
                        int kcol = j64 + n * 8 + 2 * c4l;
                        if (kcol > r0)         sf[mt][n][0] = -1e30f;
                        if (kcol + 1 > r0)     sf[mt][n][1] = -1e30f;
                        if (kcol > r0 + 8)     sf[mt][n][2] = -1e30f;
                        if (kcol + 1 > r0 + 8) sf[mt][n][3] = -1e30f;
                    }
                }
            }

            // ---- online softmax: max (fp32) + exp (f16x2) ----
            float alpha[2][2];
            uint32_t pa[2][4][4];   // MMA2 A-fragments (P in fp16)
#pragma unroll
            for (int mt = 0; mt < 2; mt++) {
#pragma unroll
                for (int hf = 0; hf < 2; hf++) {
                    float mx = -1e30f;
#pragma unroll
                    for (int n = 0; n < 8; n++)
                        mx = fmaxf(mx, fmaxf(sf[mt][n][2 * hf], sf[mt][n][2 * hf + 1]));
                    mx = fmaxf(mx, __shfl_xor_sync(0xffffffffu, mx, 1));
                    mx = fmaxf(mx, __shfl_xor_sync(0xffffffffu, mx, 2));
                    float mn = fmaxf(m_s[mt][hf], mx);
                    alpha[mt][hf] = ex2f(m_s[mt][hf] - mn);
                    m_s[mt][hf] = mn;
                }
                // pack (s - m) to half2, exp2 in f16x2 -> P fragment
#pragma unroll
                for (int kk = 0; kk < 4; kk++) {
                    int n0 = 2 * kk, n1 = 2 * kk + 1;
                    pa[mt][kk][0] = h2ex2(packh2(sf[mt][n0][0] - m_s[mt][0],
                                                 sf[mt][n0][1] - m_s[mt][0]));
                    pa[mt][kk][1] = h2ex2(packh2(sf[mt][n0][2] - m_s[mt][1],
                                                 sf[mt][n0][3] - m_s[mt][1]));
                    pa[mt][kk][2] = h2ex2(packh2(sf[mt][n1][0] - m_s[mt][0],
                                                 sf[mt][n1][1] - m_s[mt][0]));
                    pa[mt][kk][3] = h2ex2(packh2(sf[mt][n1][2] - m_s[mt][1],
                                                 sf[mt][n1][3] - m_s[mt][1]));
                }
            }

            // rescale O and l accumulators
#pragma unroll
            for (int mt = 0; mt < 2; mt++) {
#pragma unroll
                for (int n = 0; n < 8; n++) {
                    of[mt][n][0] *= alpha[mt][0];
                    of[mt][n][1] *= alpha[mt][0];
                    of[mt][n][2] *= alpha[mt][1];
                    of[mt][n][3] *= alpha[mt][1];
                }
                lf[mt][0] *= alpha[mt][0];
                lf[mt][1] *= alpha[mt][0];
                lf[mt][2] *= alpha[mt][1];
                lf[mt][3] *= alpha[mt][1];
            }

            // ---- MMA2: O += P * V ; l += P * 1 ----
            const uint32_t vbase = sb + VOFF(buf) + lm_lane;
#pragma unroll
            for (int n = 0; n < 8; n++) {
                uint32_t vf[8];
                ldsm4(vf,     vbase + (uint32_t)n * (8u * ROWB));
                ldsm4(vf + 4, vbase + (uint32_t)n * (8u * ROWB) + 64u);
#pragma unroll
                for (int kk = 0; kk < 4; kk++) {
                    mma16(of[0][n], pa[0][kk], vf[2 * kk], vf[2 * kk + 1]);
                    mma16(of[1][n], pa[1][kk], vf[2 * kk], vf[2 * kk + 1]);
                }
            }
#pragma unroll
            for (int kk = 0; kk < 4; kk++) {
                mma16(lf[0], pa[0][kk], ONES2, ONES2);
                mma16(lf[1], pa[1][kk], ONES2, ONES2);
            }
        }
        __syncthreads();
    }

    // ---- epilogue ----
    float inv[2][2];
#pragma unroll
    for (int mt = 0; mt < 2; mt++) {
        inv[mt][0] = 1.0f / lf[mt][0];
        inv[mt][1] = 1.0f / lf[mt][2];
    }
    float* Ob = Ogm + ((size_t)b * S_LEN) * str + (size_t)h * HD;
#pragma unroll
    for (int mt = 0; mt < 2; mt++) {
        float* o0 = Ob + (size_t)(qbase + mt * 16 + g) * str;
        float* o1 = o0 + 8 * str;
#pragma unroll
        for (int n = 0; n < 8; n++) {
            int d0 = n * 8 + 2 * c4l;
            *(float2*)(o0 + d0) = make_float2(of[mt][n][0] * inv[mt][0],
                                              of[mt][n][1] * inv[mt][0]);
            *(float2*)(o1 + d0) = make_float2(of[mt][n][2] * inv[mt][1],
                                              of[mt][n][3] * inv[mt][1]);
        }
    }
}

extern "C" void kernel_launch(void* const* d_in, const int* in_sizes, int n_in,
                              void* d_out, int out_size) {
    const float* Q = (const float*)d_in[0];
    const float* K = (const float*)d_in[1];
    const float* V = (const float*)d_in[2];
    float* O = (float*)d_out;

    int B = in_sizes[0] / (S_LEN * NHEAD * HD);  // = 2

    dim3 cgrid(S_LEN / 64, NHEAD, B);
    convert_kv<<<cgrid, 128>>>(K, V);

    cudaFuncSetAttribute(fa_mma_f16, cudaFuncAttributeMaxDynamicSharedMemorySize, SMEM_BYTES);
    dim3 grid(S_LEN / QT, NHEAD, B);
    fa_mma_f16<<<grid, NTHR, SMEM_BYTES>>>(Q, O);
}